// round 16
// baseline (speedup 1.0000x reference)
#include <cuda_runtime.h>
#include <math.h>
#include <stdint.h>

#define D_    1024
#define B_    4
#define T_    2048
#define M_TOTAL (B_*T_)   // 8192 rows
#define NPAIR (M_TOTAL/2) // 4096

#define CCHUNK 64         // carry T-chunk
#define WARM   64         // d^64 ~ 3e-10: exact to fp32
#define NCARRY ((T_/CCHUNK)*B_)   // 128 carry CTAs

// ---------------- device scratch ----------------
__device__ __align__(16) float2 Gspec_perm[D_];              // permuted G spectrum
__device__ __align__(16) float  carry_buf[(NPAIR + 1) * D_]; // h at every 2-row boundary

__host__ __device__ constexpr int br5(int x) {
    return ((x & 1) << 4) | ((x & 2) << 2) | (x & 4) | ((x & 8) >> 2) | ((x & 16) >> 4);
}
// omega_32^m (m=0..15), exact-to-fp32 constants
__device__ constexpr float W32R[16] = {
    1.0f, 0.98078528040323044f, 0.92387953251128674f, 0.83146961230254524f,
    0.70710678118654757f, 0.55557023301960229f, 0.38268343236508984f, 0.19509032201612833f,
    0.0f, -0.19509032201612819f, -0.38268343236508973f, -0.55557023301960196f,
    -0.70710678118654746f, -0.83146961230254524f, -0.92387953251128674f, -0.98078528040323044f };
__device__ constexpr float W32I[16] = {
    0.0f, -0.19509032201612825f, -0.38268343236508978f, -0.55557023301960218f,
    -0.70710678118654757f, -0.83146961230254524f, -0.92387953251128674f, -0.98078528040323044f,
    -1.0f, -0.98078528040323044f, -0.92387953251128674f, -0.83146961230254546f,
    -0.70710678118654757f, -0.55557023301960218f, -0.38268343236508989f, -0.19509032201612861f };

#define PI2F 6.2831853071795864769f

// ---------------------------------------------------------------------------
// In-register DIF FFT32 (natural in; reg p holds bin br5(p) out). Proven R5-R15.
// ---------------------------------------------------------------------------
__device__ __forceinline__ void fft32_reg(float zr[32], float zi[32]) {
    #pragma unroll
    for (int s = 0; s < 5; ++s) {
        const int h = 16 >> s;
        #pragma unroll
        for (int b = 0; b < 32; b += 2 * h) {
            #pragma unroll
            for (int j = 0; j < 16; ++j) {
                if (j < h) {
                    const int p = b + j, q = p + h;
                    const float ur = zr[p], ui = zi[p];
                    const float vr = zr[q], vi = zi[q];
                    zr[p] = ur + vr; zi[p] = ui + vi;
                    const float tr = ur - vr, ti = ui - vi;
                    const int m = j << s;
                    const float wr = W32R[m], wi = W32I[m];
                    zr[q] = tr * wr - ti * wi;
                    zi[q] = tr * wi + ti * wr;
                }
            }
        }
    }
}

__device__ __forceinline__ void twiddle1024(float zr[32], float zi[32],
                                            float w1x, float w1y) {
    const float w2r = w1x * w1x - w1y * w1y, w2i = 2.f * w1x * w1y;
    const float w3r = w2r * w1x - w2i * w1y, w3i = w2r * w1y + w2i * w1x;
    const float w4r = w2r * w2r - w2i * w2i, w4i = 2.f * w2r * w2i;
    float cr[4] = {1.f, w1x, w2r, w3r};
    float ci[4] = {0.f, w1y, w2i, w3i};
    #pragma unroll
    for (int j = 0; j < 8; ++j) {
        #pragma unroll
        for (int r = 0; r < 4; ++r) {
            const int p = br5(4 * j + r);
            const float ar = zr[p], ai = zi[p];
            zr[p] = ar * cr[r] - ai * ci[r];
            zi[p] = ar * ci[r] + ai * cr[r];
            const float nr = cr[r] * w4r - ci[r] * w4i;
            ci[r] = cr[r] * w4i + ci[r] * w4r;
            cr[r] = nr;
        }
    }
}

__device__ __forceinline__ void transpose32(float2* bb, float zr[32], float zi[32], int lane) {
    __syncwarp();
    #pragma unroll
    for (int k2 = 0; k2 < 32; ++k2) {
        const int p = br5(k2);
        bb[k2 * 33 + lane] = make_float2(zr[p], zi[p]);
    }
    __syncwarp();
    #pragma unroll
    for (int r = 0; r < 32; ++r) {
        const float2 t = bb[lane * 33 + r];
        zr[r] = t.x; zi[r] = t.y;
    }
}

// warp 1024-pt FFT. in: lane=n&31, reg=n>>5. out: Z[k] at lane=k&31, reg=br5(k>>5)
__device__ __forceinline__ void fft1024(float2* bb, float zr[32], float zi[32],
                                        int lane, float w1x, float w1y) {
    fft32_reg(zr, zi);
    twiddle1024(zr, zi, w1x, w1y);
    transpose32(bb, zr, zi, lane);
    fft32_reg(zr, zi);
}

// ---------------------------------------------------------------------------
// G-spectrum build body (one warp): Z = FFT(bk + i*uk), Hermitian split,
// Gspec_perm[br5(k>>5)*32 + (k&31)] = gate * BK[k] * conj(UK[k]) / 1024
// ---------------------------------------------------------------------------
__device__ void build_gspec_warp(const float* __restrict__ bk,
                                 const float* __restrict__ uk,
                                 const float* __restrict__ gate,
                                 float2* bbs, float* zsr, float* zsi, int lane) {
    float zr[32], zi[32];
    #pragma unroll
    for (int r = 0; r < 32; ++r) {
        zr[r] = __ldg(&bk[lane + 32 * r]);
        zi[r] = __ldg(&uk[lane + 32 * r]);
    }
    float w1x, w1y;
    sincosf(-PI2F * (float)lane * (1.0f / 1024.0f), &w1y, &w1x);
    fft1024(bbs, zr, zi, lane, w1x, w1y);

    #pragma unroll
    for (int p = 0; p < 32; ++p) {
        const int k = lane + 32 * br5(p);
        zsr[k] = zr[p]; zsi[k] = zi[p];
    }
    __syncwarp();

    const float sc = gate[0] * (1.0f / 1024.0f);
    #pragma unroll
    for (int j = 0; j < 32; ++j) {
        const int k  = 32 * j + lane;
        const int km = (D_ - k) & (D_ - 1);
        const float a = zsr[k],  b = zsi[k];
        const float c = zsr[km], d = zsi[km];
        const float bkr = 0.5f * (a + c), bki = 0.5f * (b - d);
        const float ukr = 0.5f * (b + d), uki = 0.5f * (c - a);
        const float gr = sc * (bkr * ukr + bki * uki);   // BK * conj(UK)
        const float gi = sc * (bki * ukr - bkr * uki);
        Gspec_perm[br5(j) * 32 + lane] = make_float2(gr, gi);
    }
}

// ---------------------------------------------------------------------------
// Fused pre-pass: CTAs 0..127 = carry scan (pair-boundary emission, MLP-8
// batched loads); CTA 128 = G-spectrum build.
// carry_buf[p] = h[2p-1]. Pairs at batch starts use zero carry in conv.
// ---------------------------------------------------------------------------
__global__ void prepass_kernel(const float* __restrict__ x,
                               const float* __restrict__ decay_p,
                               const float* __restrict__ bk,
                               const float* __restrict__ uk,
                               const float* __restrict__ gate) {
    __shared__ __align__(16) float2 bbs[1056];
    __shared__ float zsr[D_], zsi[D_];

    const int cta = blockIdx.x;
    const int tid = threadIdx.x;

    if (cta == NCARRY) {
        if (tid < 32) build_gspec_warp(bk, uk, gate, bbs, zsr, zsi, tid);
        return;
    }

    const int b   = cta >> 5;              // 32 chunks per batch
    const int cx  = cta & 31;
    const int t0g = b * T_ + cx * CCHUNK;
    const float d = 1.0f / (1.0f + expf(-decay_p[0]));

    float4 acc = make_float4(0.f, 0.f, 0.f, 0.f);
    const float* xp;
    if (cx > 0) {
        xp = x + (size_t)(t0g - WARM) * D_ + tid * 4;
        #pragma unroll 1
        for (int bi = 0; bi < WARM / 8; ++bi) {
            float4 v[8];
            #pragma unroll
            for (int j = 0; j < 8; ++j)
                v[j] = *reinterpret_cast<const float4*>(xp + (size_t)j * D_);
            xp += 8 * D_;
            #pragma unroll
            for (int j = 0; j < 8; ++j) {
                acc.x = fmaf(acc.x, d, v[j].x); acc.y = fmaf(acc.y, d, v[j].y);
                acc.z = fmaf(acc.z, d, v[j].z); acc.w = fmaf(acc.w, d, v[j].w);
            }
        }
    } else {
        xp = x + (size_t)t0g * D_ + tid * 4;
    }
    // main chunk: batched 8-row loads, store carry at every odd global row
    #pragma unroll 1
    for (int bi = 0; bi < CCHUNK / 8; ++bi) {
        float4 v[8];
        #pragma unroll
        for (int j = 0; j < 8; ++j)
            v[j] = *reinterpret_cast<const float4*>(xp + (size_t)j * D_);
        xp += 8 * D_;
        #pragma unroll
        for (int j = 0; j < 8; ++j) {
            acc.x = fmaf(acc.x, d, v[j].x); acc.y = fmaf(acc.y, d, v[j].y);
            acc.z = fmaf(acc.z, d, v[j].z); acc.w = fmaf(acc.w, d, v[j].w);
            if (j & 1) {
                const int p = (t0g + bi * 8 + j + 1) >> 1;
                *reinterpret_cast<float4*>(&carry_buf[(size_t)p * D_ + tid * 4]) = acc;
            }
        }
    }
}

// ---------------------------------------------------------------------------
// conv: warp = pair (rows 2p, 2p+1). Inline scan during register load.
// (128,3): ~170-reg budget — spill-free (R11 evidence) AND 3 CTAs/SM.
// ---------------------------------------------------------------------------
__global__ void __launch_bounds__(128, 3)
conv_kernel(const float* __restrict__ x, float* __restrict__ out,
            const float* __restrict__ decay_p) {
    __shared__ __align__(16) float2 bounce[4 * 1056];

    const int wid  = threadIdx.x >> 5;
    const int lane = threadIdx.x & 31;
    float2* bb = bounce + wid * 1056;

    const int pair = blockIdx.x * 4 + wid;
    const float dcy = 1.0f / (1.0f + expf(-decay_p[0]));

    const float* xa = x + (size_t)(2 * pair) * D_;
    const float* xb = xa + D_;

    float zr[32], zi[32];
    if ((pair & (T_ / 2 - 1)) == 0) {
        #pragma unroll
        for (int r = 0; r < 32; ++r) {
            const float h0 = xa[lane + 32 * r];
            zr[r] = h0;
            zi[r] = fmaf(h0, dcy, xb[lane + 32 * r]);
        }
    } else {
        const float* cp = carry_buf + (size_t)pair * D_;
        #pragma unroll
        for (int r = 0; r < 32; ++r) {
            const int m = lane + 32 * r;
            const float h0 = fmaf(cp[m], dcy, xa[m]);
            zr[r] = h0;
            zi[r] = fmaf(h0, dcy, xb[m]);
        }
    }

    float w1x, w1y;
    sincosf(-PI2F * (float)lane * (1.0f / 1024.0f), &w1y, &w1x);

    // forward FFT
    fft1024(bb, zr, zi, lane, w1x, w1y);

    // multiply by G (layout-matched) and conjugate (inverse via conj trick)
    #pragma unroll
    for (int p = 0; p < 32; ++p) {
        const float2 g = __ldg(&Gspec_perm[p * 32 + lane]);
        const float vr = zr[p] * g.x - zi[p] * g.y;
        const float vi = zr[p] * g.y + zi[p] * g.x;
        zr[p] = vr;
        zi[p] = -vi;
    }
    // reorder regs for inverse input (bit-reversal involution, free)
    #pragma unroll
    for (int p = 0; p < 32; ++p) {
        const int qq = br5(p);
        if (p < qq) {
            float t;
            t = zr[p]; zr[p] = zr[qq]; zr[qq] = t;
            t = zi[p]; zi[p] = zi[qq]; zi[qq] = t;
        }
    }
    // inverse = conj(FFT(conj(V))); 1/N folded into G
    fft1024(bb, zr, zi, lane, w1x, w1y);

    // epilogue: out = x + v (x rows L1-hot from the load above)
    float* oa = out + (size_t)(2 * pair) * D_;
    float* ob = oa + D_;
    #pragma unroll
    for (int c = 0; c < 32; ++c) {
        const int p = br5(c);
        const int m = lane + 32 * c;
        oa[m] = xa[m] + zr[p];
        ob[m] = xb[m] - zi[p];
    }
}

// ---------------------------------------------------------------------------
extern "C" void kernel_launch(void* const* d_in, const int* in_sizes, int n_in,
                              void* d_out, int out_size) {
    const float* x     = (const float*)d_in[0];
    const float* bk    = (const float*)d_in[1];
    const float* uk    = (const float*)d_in[2];
    const float* gate  = (const float*)d_in[3];
    const float* decay = (const float*)d_in[4];
    float* out = (float*)d_out;

    prepass_kernel<<<NCARRY + 1, 256>>>(x, decay, bk, uk, gate);
    conv_kernel<<<NPAIR / 4, 128>>>(x, out, decay);
}

// round 17
// speedup vs baseline: 1.4312x; 1.4312x over previous
#include <cuda_runtime.h>
#include <math.h>
#include <stdint.h>

#define D_    1024
#define B_    4
#define T_    2048
#define M_TOTAL (B_*T_)   // 8192 rows

#define CCHUNK 64         // carry T-chunk
#define WARM   64         // d^64 ~ 3e-10: exact to fp32
#define NCARRY ((T_/CCHUNK)*B_)   // 128 carry CTAs

// ---------------- device scratch ----------------
__device__ __align__(16) float2 Gspec_perm[D_];              // permuted G spectrum
__device__ __align__(16) float  carry_buf[1025 * D_];        // h at 8-row boundaries

__host__ __device__ constexpr int br5(int x) {
    return ((x & 1) << 4) | ((x & 2) << 2) | (x & 4) | ((x & 8) >> 2) | ((x & 16) >> 4);
}
// omega_32^m (m=0..15), exact-to-fp32 constants
__device__ constexpr float W32R[16] = {
    1.0f, 0.98078528040323044f, 0.92387953251128674f, 0.83146961230254524f,
    0.70710678118654757f, 0.55557023301960229f, 0.38268343236508984f, 0.19509032201612833f,
    0.0f, -0.19509032201612819f, -0.38268343236508973f, -0.55557023301960196f,
    -0.70710678118654746f, -0.83146961230254524f, -0.92387953251128674f, -0.98078528040323044f };
__device__ constexpr float W32I[16] = {
    0.0f, -0.19509032201612825f, -0.38268343236508978f, -0.55557023301960218f,
    -0.70710678118654757f, -0.83146961230254524f, -0.92387953251128674f, -0.98078528040323044f,
    -1.0f, -0.98078528040323044f, -0.92387953251128674f, -0.83146961230254546f,
    -0.70710678118654757f, -0.55557023301960218f, -0.38268343236508989f, -0.19509032201612861f };

#define PI2F 6.2831853071795864769f

// ---------------------------------------------------------------------------
// In-register DIF FFT32 (natural in; reg p holds bin br5(p) out). Proven R5-R16.
// ---------------------------------------------------------------------------
__device__ __forceinline__ void fft32_reg(float zr[32], float zi[32]) {
    #pragma unroll
    for (int s = 0; s < 5; ++s) {
        const int h = 16 >> s;
        #pragma unroll
        for (int b = 0; b < 32; b += 2 * h) {
            #pragma unroll
            for (int j = 0; j < 16; ++j) {
                if (j < h) {
                    const int p = b + j, q = p + h;
                    const float ur = zr[p], ui = zi[p];
                    const float vr = zr[q], vi = zi[q];
                    zr[p] = ur + vr; zi[p] = ui + vi;
                    const float tr = ur - vr, ti = ui - vi;
                    const int m = j << s;
                    const float wr = W32R[m], wi = W32I[m];
                    zr[q] = tr * wr - ti * wi;
                    zi[q] = tr * wi + ti * wr;
                }
            }
        }
    }
}

__device__ __forceinline__ void twiddle1024(float zr[32], float zi[32],
                                            float w1x, float w1y) {
    const float w2r = w1x * w1x - w1y * w1y, w2i = 2.f * w1x * w1y;
    const float w3r = w2r * w1x - w2i * w1y, w3i = w2r * w1y + w2i * w1x;
    const float w4r = w2r * w2r - w2i * w2i, w4i = 2.f * w2r * w2i;
    float cr[4] = {1.f, w1x, w2r, w3r};
    float ci[4] = {0.f, w1y, w2i, w3i};
    #pragma unroll
    for (int j = 0; j < 8; ++j) {
        #pragma unroll
        for (int r = 0; r < 4; ++r) {
            const int p = br5(4 * j + r);
            const float ar = zr[p], ai = zi[p];
            zr[p] = ar * cr[r] - ai * ci[r];
            zi[p] = ar * ci[r] + ai * cr[r];
            const float nr = cr[r] * w4r - ci[r] * w4i;
            ci[r] = cr[r] * w4i + ci[r] * w4r;
            cr[r] = nr;
        }
    }
}

__device__ __forceinline__ void transpose32(float2* bb, float zr[32], float zi[32], int lane) {
    __syncwarp();
    #pragma unroll
    for (int k2 = 0; k2 < 32; ++k2) {
        const int p = br5(k2);
        bb[k2 * 33 + lane] = make_float2(zr[p], zi[p]);
    }
    __syncwarp();
    #pragma unroll
    for (int r = 0; r < 32; ++r) {
        const float2 t = bb[lane * 33 + r];
        zr[r] = t.x; zi[r] = t.y;
    }
}

// warp 1024-pt FFT. in: lane=n&31, reg=n>>5. out: Z[k] at lane=k&31, reg=br5(k>>5)
__device__ __forceinline__ void fft1024(float2* bb, float zr[32], float zi[32],
                                        int lane, float w1x, float w1y) {
    fft32_reg(zr, zi);
    twiddle1024(zr, zi, w1x, w1y);
    transpose32(bb, zr, zi, lane);
    fft32_reg(zr, zi);
}

// ---------------------------------------------------------------------------
// G-spectrum build body (one warp): Z = FFT(bk + i*uk), Hermitian split,
// Gspec_perm[br5(k>>5)*32 + (k&31)] = gate * BK[k] * conj(UK[k]) / 1024
// ---------------------------------------------------------------------------
__device__ void build_gspec_warp(const float* __restrict__ bk,
                                 const float* __restrict__ uk,
                                 const float* __restrict__ gate,
                                 float2* bbs, float* zsr, float* zsi, int lane) {
    float zr[32], zi[32];
    #pragma unroll
    for (int r = 0; r < 32; ++r) {
        zr[r] = __ldg(&bk[lane + 32 * r]);
        zi[r] = __ldg(&uk[lane + 32 * r]);
    }
    float w1x, w1y;
    sincosf(-PI2F * (float)lane * (1.0f / 1024.0f), &w1y, &w1x);
    fft1024(bbs, zr, zi, lane, w1x, w1y);

    #pragma unroll
    for (int p = 0; p < 32; ++p) {
        const int k = lane + 32 * br5(p);
        zsr[k] = zr[p]; zsi[k] = zi[p];
    }
    __syncwarp();

    const float sc = gate[0] * (1.0f / 1024.0f);
    #pragma unroll
    for (int j = 0; j < 32; ++j) {
        const int k  = 32 * j + lane;
        const int km = (D_ - k) & (D_ - 1);
        const float a = zsr[k],  b = zsi[k];
        const float c = zsr[km], d = zsi[km];
        const float bkr = 0.5f * (a + c), bki = 0.5f * (b - d);
        const float ukr = 0.5f * (b + d), uki = 0.5f * (c - a);
        const float gr = sc * (bkr * ukr + bki * uki);   // BK * conj(UK)
        const float gi = sc * (bki * ukr - bkr * uki);
        Gspec_perm[br5(j) * 32 + lane] = make_float2(gr, gi);
    }
}

// ---------------------------------------------------------------------------
// Fused pre-pass: CTAs 0..127 = carry scan emitting h at 8-row boundaries
// (batched MLP-8 loads, store AFTER each 8-FMA block); CTA 128 = G build.
// carry_buf[q] = h[8q-1] (global row index).
// ---------------------------------------------------------------------------
__global__ void prepass_kernel(const float* __restrict__ x,
                               const float* __restrict__ decay_p,
                               const float* __restrict__ bk,
                               const float* __restrict__ uk,
                               const float* __restrict__ gate) {
    __shared__ __align__(16) float2 bbs[1056];
    __shared__ float zsr[D_], zsi[D_];

    const int cta = blockIdx.x;
    const int tid = threadIdx.x;

    if (cta == NCARRY) {
        if (tid < 32) build_gspec_warp(bk, uk, gate, bbs, zsr, zsi, tid);
        return;
    }

    const int b   = cta >> 5;              // 32 chunks per batch
    const int cx  = cta & 31;
    const int t0g = b * T_ + cx * CCHUNK;
    const float d = 1.0f / (1.0f + expf(-decay_p[0]));

    float4 acc = make_float4(0.f, 0.f, 0.f, 0.f);
    const float* xp;
    if (cx > 0) {
        xp = x + (size_t)(t0g - WARM) * D_ + tid * 4;
        #pragma unroll 1
        for (int bi = 0; bi < WARM / 8; ++bi) {
            float4 v[8];
            #pragma unroll
            for (int j = 0; j < 8; ++j)
                v[j] = *reinterpret_cast<const float4*>(xp + (size_t)j * D_);
            xp += 8 * D_;
            #pragma unroll
            for (int j = 0; j < 8; ++j) {
                acc.x = fmaf(acc.x, d, v[j].x); acc.y = fmaf(acc.y, d, v[j].y);
                acc.z = fmaf(acc.z, d, v[j].z); acc.w = fmaf(acc.w, d, v[j].w);
            }
        }
    } else {
        xp = x + (size_t)t0g * D_ + tid * 4;
    }
    // main chunk: batched 8-row loads; carry store after each 8-FMA block
    #pragma unroll 1
    for (int bi = 0; bi < CCHUNK / 8; ++bi) {
        float4 v[8];
        #pragma unroll
        for (int j = 0; j < 8; ++j)
            v[j] = *reinterpret_cast<const float4*>(xp + (size_t)j * D_);
        xp += 8 * D_;
        #pragma unroll
        for (int j = 0; j < 8; ++j) {
            acc.x = fmaf(acc.x, d, v[j].x); acc.y = fmaf(acc.y, d, v[j].y);
            acc.z = fmaf(acc.z, d, v[j].z); acc.w = fmaf(acc.w, d, v[j].w);
        }
        const int q = (t0g + bi * 8 + 8) >> 3;
        *reinterpret_cast<float4*>(&carry_buf[(size_t)q * D_ + tid * 4]) = acc;
    }
}

// ---------------------------------------------------------------------------
// Fused conv — EXACT R11 configuration (best measured: 27.6 us, 168 regs).
// CTA = 4 warps handles 8 rows: phase-1 in-SMEM scan, then per-warp pair FFT.
// ---------------------------------------------------------------------------
__global__ void __launch_bounds__(128)
conv_kernel(const float* __restrict__ x, float* __restrict__ out,
            const float* __restrict__ decay_p) {
    __shared__ __align__(16) float2 bounce[4 * 1056];
    float* sh = (float*)bounce;

    const int tid  = threadIdx.x;
    const int wid  = tid >> 5;
    const int lane = tid & 31;
    const int q    = blockIdx.x;
    const int row0 = q * 8;
    float2* bb = bounce + wid * 1056;

    const float dcy = 1.0f / (1.0f + expf(-decay_p[0]));

    // phase 1: scan 8 rows into sh
    {
        float4 a0, a1;
        if ((row0 & (T_ - 1)) != 0) {
            a0 = *reinterpret_cast<const float4*>(&carry_buf[(size_t)q * D_ + tid * 4]);
            a1 = *reinterpret_cast<const float4*>(&carry_buf[(size_t)q * D_ + 512 + tid * 4]);
        } else {
            a0 = make_float4(0.f, 0.f, 0.f, 0.f);
            a1 = a0;
        }
        const float* xp = x + (size_t)row0 * D_ + tid * 4;
        #pragma unroll
        for (int r = 0; r < 8; ++r) {
            const float4 v0 = *reinterpret_cast<const float4*>(xp);
            const float4 v1 = *reinterpret_cast<const float4*>(xp + 512);
            a0.x = fmaf(a0.x, dcy, v0.x); a0.y = fmaf(a0.y, dcy, v0.y);
            a0.z = fmaf(a0.z, dcy, v0.z); a0.w = fmaf(a0.w, dcy, v0.w);
            a1.x = fmaf(a1.x, dcy, v1.x); a1.y = fmaf(a1.y, dcy, v1.y);
            a1.z = fmaf(a1.z, dcy, v1.z); a1.w = fmaf(a1.w, dcy, v1.w);
            *reinterpret_cast<float4*>(&sh[r * D_ + tid * 4])       = a0;
            *reinterpret_cast<float4*>(&sh[r * D_ + 512 + tid * 4]) = a1;
            xp += D_;
        }
    }
    __syncthreads();

    float zr[32], zi[32];
    {
        const float* ra = sh + (2 * wid) * D_;
        const float* rb = ra + D_;
        #pragma unroll
        for (int r = 0; r < 32; ++r) {
            zr[r] = ra[lane + 32 * r];
            zi[r] = rb[lane + 32 * r];
        }
    }
    __syncthreads();

    float w1x, w1y;
    sincosf(-PI2F * (float)lane * (1.0f / 1024.0f), &w1y, &w1x);

    fft1024(bb, zr, zi, lane, w1x, w1y);

    #pragma unroll
    for (int p = 0; p < 32; ++p) {
        const float2 g = __ldg(&Gspec_perm[p * 32 + lane]);
        const float vr = zr[p] * g.x - zi[p] * g.y;
        const float vi = zr[p] * g.y + zi[p] * g.x;
        zr[p] = vr;
        zi[p] = -vi;
    }
    #pragma unroll
    for (int p = 0; p < 32; ++p) {
        const int qq = br5(p);
        if (p < qq) {
            float t;
            t = zr[p]; zr[p] = zr[qq]; zr[qq] = t;
            t = zi[p]; zi[p] = zi[qq]; zi[qq] = t;
        }
    }
    fft1024(bb, zr, zi, lane, w1x, w1y);

    const int pair = q * 4 + wid;
    const float* xa = x + (size_t)(2 * pair) * D_;
    const float* xb = xa + D_;
    float* oa = out + (size_t)(2 * pair) * D_;
    float* ob = oa + D_;
    #pragma unroll
    for (int c = 0; c < 32; ++c) {
        const int p = br5(c);
        const int m = lane + 32 * c;
        oa[m] = xa[m] + zr[p];
        ob[m] = xb[m] - zi[p];
    }
}

// ---------------------------------------------------------------------------
extern "C" void kernel_launch(void* const* d_in, const int* in_sizes, int n_in,
                              void* d_out, int out_size) {
    const float* x     = (const float*)d_in[0];
    const float* bk    = (const float*)d_in[1];
    const float* uk    = (const float*)d_in[2];
    const float* gate  = (const float*)d_in[3];
    const float* decay = (const float*)d_in[4];
    float* out = (float*)d_out;

    prepass_kernel<<<NCARRY + 1, 256>>>(x, decay, bk, uk, gate);
    conv_kernel<<<M_TOTAL / 8, 128>>>(x, out, decay);
}